// round 1
// baseline (speedup 1.0000x reference)
#include <cuda_runtime.h>
#include <cuda_bf16.h>
#include <math.h>

#define BATCH 64
#define SEQ   196
#define DIMC  768
#define HEADS 12
#define HD    64
#define QKV3  2304           // 3*DIMC
#define BN    (BATCH*SEQ)    // 12544
#define SCALE 0.125f         // HD^-0.5

// ---------------- scratch (no allocation allowed; __device__ globals) -------
__device__ float g_qkv[(size_t)BATCH * SEQ * QKV3];           // [BN, 2304]
__device__ float g_attn[(size_t)BATCH * HEADS * SEQ * SEQ];   // [B,H,N,M]
__device__ float g_ao[(size_t)BATCH * SEQ * DIMC];            // [BN, 768]

// ---------------- SGEMM: C[M,N] = A[M,K] @ B[K,N] (+bias) -------------------
// 64x64 block tile, 16 k-tile, 256 threads, 4x4 micro-tile per thread.
// Requires M%64==0, N%64==0, K%16==0 (true for both uses).
__global__ __launch_bounds__(256)
void sgemm_kernel(const float* __restrict__ A, const float* __restrict__ B,
                  const float* __restrict__ bias, float* __restrict__ C,
                  int M, int N, int K, int useBias)
{
    __shared__ float As[16][68];   // padded: transposed-store conflicts -> 2-way
    __shared__ float Bs[16][64];

    int tid = threadIdx.x;
    int tx = tid & 15;
    int ty = tid >> 4;
    int n0 = blockIdx.x * 64;
    int m0 = blockIdx.y * 64;

    int arow = tid >> 2;          // 0..63
    int akc  = (tid & 3) * 4;     // 0..12
    int brow = tid >> 4;          // 0..15
    int bcol = (tid & 15) * 4;    // 0..60

    float acc[4][4];
#pragma unroll
    for (int i = 0; i < 4; i++)
#pragma unroll
        for (int j = 0; j < 4; j++) acc[i][j] = 0.f;

    for (int k0 = 0; k0 < K; k0 += 16) {
        float4 av = *(const float4*)(A + (size_t)(m0 + arow) * K + k0 + akc);
        float4 bv = *(const float4*)(B + (size_t)(k0 + brow) * N + n0 + bcol);
        As[akc + 0][arow] = av.x;
        As[akc + 1][arow] = av.y;
        As[akc + 2][arow] = av.z;
        As[akc + 3][arow] = av.w;
        *(float4*)&Bs[brow][bcol] = bv;
        __syncthreads();

#pragma unroll
        for (int kk = 0; kk < 16; kk++) {
            float4 a = *(const float4*)&As[kk][ty * 4];
            float4 b = *(const float4*)&Bs[kk][tx * 4];
            float ar[4] = {a.x, a.y, a.z, a.w};
            float br[4] = {b.x, b.y, b.z, b.w};
#pragma unroll
            for (int i = 0; i < 4; i++)
#pragma unroll
                for (int j = 0; j < 4; j++) acc[i][j] += ar[i] * br[j];
        }
        __syncthreads();
    }

#pragma unroll
    for (int i = 0; i < 4; i++) {
        int m = m0 + ty * 4 + i;
        float4 r;
        r.x = acc[i][0]; r.y = acc[i][1]; r.z = acc[i][2]; r.w = acc[i][3];
        if (useBias) {
            const float* bp = bias + n0 + tx * 4;
            r.x += bp[0]; r.y += bp[1]; r.z += bp[2]; r.w += bp[3];
        }
        *(float4*)(C + (size_t)m * N + n0 + tx * 4) = r;
    }
}

// ---------------- scores: S[b,h,n,m] = SCALE * dot(q[n], k[m]) --------------
// grid (7,7,B*H); 32x32 tile, full K=64 in smem; 256 threads, 2x2 micro-tile.
__global__ __launch_bounds__(256)
void scores_kernel(const float* __restrict__ qkv, float* __restrict__ attn)
{
    __shared__ float Qs[64][33];
    __shared__ float Ks[64][33];

    int bh = blockIdx.z;
    int b = bh / HEADS, h = bh % HEADS;
    int n0 = blockIdx.y * 32;
    int m0 = blockIdx.x * 32;
    const float* qb = qkv + (size_t)b * SEQ * QKV3 + h * HD;
    const float* kb = qb + DIMC;

    int tid = threadIdx.x;
#pragma unroll
    for (int it = 0; it < 2; it++) {
        int idx = it * 256 + tid;       // 0..511 (float4 index)
        int row = idx >> 4;             // 0..31
        int kc  = (idx & 15) * 4;       // 0..60
        float4 qv = make_float4(0.f, 0.f, 0.f, 0.f);
        float4 kv = make_float4(0.f, 0.f, 0.f, 0.f);
        int nq = n0 + row, nk = m0 + row;
        if (nq < SEQ) qv = *(const float4*)(qb + (size_t)nq * QKV3 + kc);
        if (nk < SEQ) kv = *(const float4*)(kb + (size_t)nk * QKV3 + kc);
        Qs[kc + 0][row] = qv.x; Qs[kc + 1][row] = qv.y;
        Qs[kc + 2][row] = qv.z; Qs[kc + 3][row] = qv.w;
        Ks[kc + 0][row] = kv.x; Ks[kc + 1][row] = kv.y;
        Ks[kc + 2][row] = kv.z; Ks[kc + 3][row] = kv.w;
    }
    __syncthreads();

    int tx = tid & 15, ty = tid >> 4;
    float acc[2][2] = {{0.f, 0.f}, {0.f, 0.f}};
#pragma unroll
    for (int kk = 0; kk < 64; kk++) {
        float a0 = Qs[kk][ty * 2 + 0];
        float a1 = Qs[kk][ty * 2 + 1];
        float b0 = Ks[kk][tx * 2 + 0];
        float b1 = Ks[kk][tx * 2 + 1];
        acc[0][0] += a0 * b0; acc[0][1] += a0 * b1;
        acc[1][0] += a1 * b0; acc[1][1] += a1 * b1;
    }

    float* out = attn + (size_t)bh * SEQ * SEQ;
#pragma unroll
    for (int i = 0; i < 2; i++) {
        int n = n0 + ty * 2 + i;
        if (n >= SEQ) continue;
#pragma unroll
        for (int j = 0; j < 2; j++) {
            int m = m0 + tx * 2 + j;
            if (m < SEQ) out[(size_t)n * SEQ + m] = acc[i][j] * SCALE;
        }
    }
}

// ---------------- softmax (axis m) + static_a bias, in place ----------------
// one block (256 thr) per (b,h,n) row of 196
__global__ __launch_bounds__(256)
void softmax_bias_kernel(float* __restrict__ attn, const float* __restrict__ sa)
{
    int row = blockIdx.x;             // 0 .. B*H*SEQ-1
    int n   = row % SEQ;
    int bh  = row / SEQ;
    int h   = bh % HEADS;
    float* p = attn + (size_t)row * SEQ;
    int tid = threadIdx.x;

    float v = (tid < SEQ) ? p[tid] : -INFINITY;

    __shared__ float red[256];
    red[tid] = v;
    __syncthreads();
#pragma unroll
    for (int s = 128; s > 0; s >>= 1) {
        if (tid < s) red[tid] = fmaxf(red[tid], red[tid + s]);
        __syncthreads();
    }
    float mx = red[0];
    __syncthreads();

    float e = (tid < SEQ) ? __expf(v - mx) : 0.f;
    red[tid] = e;
    __syncthreads();
#pragma unroll
    for (int s = 128; s > 0; s >>= 1) {
        if (tid < s) red[tid] += red[tid + s];
        __syncthreads();
    }
    float inv = 1.f / red[0];

    if (tid < SEQ)
        p[tid] = e * inv + sa[((size_t)h * SEQ + n) * SEQ + tid];
}

// ---------------- AV: ao[b,n,h*64+d] = sum_m S[b,h,n,m] * v[b,h,m,d] --------
// grid (7, B*H); 32x64 tile over (n,d), k-loop over m in steps of 16
__global__ __launch_bounds__(256)
void av_kernel(const float* __restrict__ attn, const float* __restrict__ qkv,
               float* __restrict__ ao)
{
    __shared__ float Sts[16][33];
    __shared__ float Vts[16][64];

    int bh = blockIdx.y;
    int b = bh / HEADS, h = bh % HEADS;
    int n0 = blockIdx.x * 32;
    const float* Sb = attn + (size_t)bh * SEQ * SEQ;
    const float* Vb = qkv + (size_t)b * SEQ * QKV3 + 2 * DIMC + h * HD;

    int tid = threadIdx.x;
    int tx = tid & 15, ty = tid >> 4;
    float acc[2][4];
#pragma unroll
    for (int i = 0; i < 2; i++)
#pragma unroll
        for (int j = 0; j < 4; j++) acc[i][j] = 0.f;

    for (int k0 = 0; k0 < SEQ; k0 += 16) {
        if (tid < 128) {
            int row = tid >> 2;          // 0..31
            int kc  = (tid & 3) * 4;     // 0..12
            float4 sv = make_float4(0.f, 0.f, 0.f, 0.f);
            int n = n0 + row;
            if (n < SEQ) {
                if (k0 + kc + 3 < SEQ) {
                    sv = *(const float4*)(Sb + (size_t)n * SEQ + k0 + kc);
                } else {
                    float t[4] = {0.f, 0.f, 0.f, 0.f};
#pragma unroll
                    for (int i = 0; i < 4; i++)
                        if (k0 + kc + i < SEQ) t[i] = Sb[(size_t)n * SEQ + k0 + kc + i];
                    sv = make_float4(t[0], t[1], t[2], t[3]);
                }
            }
            Sts[kc + 0][row] = sv.x; Sts[kc + 1][row] = sv.y;
            Sts[kc + 2][row] = sv.z; Sts[kc + 3][row] = sv.w;
        }
        {
            int kk = tid >> 4;           // 0..15
            int c  = (tid & 15) * 4;     // 0..60
            float4 vv = make_float4(0.f, 0.f, 0.f, 0.f);
            if (k0 + kk < SEQ)
                vv = *(const float4*)(Vb + (size_t)(k0 + kk) * QKV3 + c);
            *(float4*)&Vts[kk][c] = vv;
        }
        __syncthreads();

#pragma unroll
        for (int kk = 0; kk < 16; kk++) {
            float a0 = Sts[kk][ty * 2 + 0];
            float a1 = Sts[kk][ty * 2 + 1];
            float4 bv = *(const float4*)&Vts[kk][tx * 4];
            acc[0][0] += a0 * bv.x; acc[0][1] += a0 * bv.y;
            acc[0][2] += a0 * bv.z; acc[0][3] += a0 * bv.w;
            acc[1][0] += a1 * bv.x; acc[1][1] += a1 * bv.y;
            acc[1][2] += a1 * bv.z; acc[1][3] += a1 * bv.w;
        }
        __syncthreads();
    }

    float* ob = ao + (size_t)b * SEQ * DIMC + h * HD;
#pragma unroll
    for (int i = 0; i < 2; i++) {
        int n = n0 + ty * 2 + i;
        if (n < SEQ) {
            float4 r = make_float4(acc[i][0], acc[i][1], acc[i][2], acc[i][3]);
            *(float4*)(ob + (size_t)n * DIMC + tx * 4) = r;
        }
    }
}

// ---------------- launch ----------------------------------------------------
extern "C" void kernel_launch(void* const* d_in, const int* in_sizes, int n_in,
                              void* d_out, int out_size)
{
    const float* x     = (const float*)d_in[0];  // [64,196,768]
    const float* Wqkv  = (const float*)d_in[1];  // [768,2304]
    const float* sa    = (const float*)d_in[2];  // [1,12,196,196]
    const float* Wproj = (const float*)d_in[3];  // [768,768]
    const float* bproj = (const float*)d_in[4];  // [768]
    float* out = (float*)d_out;                  // [64,196,768]

    void *p_qkv, *p_attn, *p_ao;
    cudaGetSymbolAddress(&p_qkv, g_qkv);
    cudaGetSymbolAddress(&p_attn, g_attn);
    cudaGetSymbolAddress(&p_ao, g_ao);
    float* qkv  = (float*)p_qkv;
    float* attn = (float*)p_attn;
    float* ao   = (float*)p_ao;

    // 1) QKV GEMM: [12544,768] @ [768,2304]
    sgemm_kernel<<<dim3(QKV3 / 64, BN / 64), 256>>>(x, Wqkv, nullptr, qkv,
                                                    BN, QKV3, DIMC, 0);
    // 2) scores
    scores_kernel<<<dim3(7, 7, BATCH * HEADS), 256>>>(qkv, attn);
    // 3) softmax + static_a
    softmax_bias_kernel<<<BATCH * HEADS * SEQ, 256>>>(attn, sa);
    // 4) AV
    av_kernel<<<dim3(7, BATCH * HEADS), 256>>>(attn, qkv, ao);
    // 5) output projection + bias
    sgemm_kernel<<<dim3(DIMC / 64, BN / 64), 256>>>(ao, Wproj, bproj, out,
                                                    BN, DIMC, DIMC, 1);
}

// round 2
// speedup vs baseline: 1.7998x; 1.7998x over previous
#include <cuda_runtime.h>
#include <cuda_bf16.h>
#include <math.h>

#define BATCH 64
#define SEQ   196
#define DIMC  768
#define HEADS 12
#define HD    64
#define QKV3  2304           // 3*DIMC
#define BN    (BATCH*SEQ)    // 12544
#define SCALE 0.125f         // HD^-0.5

// ---------------- scratch (no allocation allowed; __device__ globals) -------
__device__ float g_qkv[(size_t)BATCH * SEQ * QKV3];           // [BN, 2304]
__device__ float g_attn[(size_t)BATCH * HEADS * SEQ * SEQ];   // [B,H,N,M]
__device__ float g_ao[(size_t)BATCH * SEQ * DIMC];            // [BN, 768]

// ---------------- tf32 helpers ----------------------------------------------
__device__ __forceinline__ unsigned f2tf32(float x) {
    unsigned u;
    asm volatile("cvt.rna.tf32.f32 %0, %1;" : "=r"(u) : "f"(x));
    return u;
}

__device__ __forceinline__ void mma_tf32(float (&d)[4], const unsigned (&a)[4],
                                         const unsigned (&b)[2]) {
    asm volatile(
        "mma.sync.aligned.m16n8k8.row.col.f32.tf32.tf32.f32 "
        "{%0,%1,%2,%3}, {%4,%5,%6,%7}, {%8,%9}, {%0,%1,%2,%3};\n"
        : "+f"(d[0]), "+f"(d[1]), "+f"(d[2]), "+f"(d[3])
        : "r"(a[0]), "r"(a[1]), "r"(a[2]), "r"(a[3]), "r"(b[0]), "r"(b[1]));
}

// ---------------- TF32 GEMM: C[M,N] = A[M,K] @ B[K,N] (+bias) ---------------
// 128x64 block tile, BK=32, 256 threads = 8 warps, warp tile 32x32 (2x4 mma).
// Requires M%128==0, N%64==0, K%32==0 (holds for both uses).
#define TBM 128
#define TBN 64
#define TBK 32
#define AS_STRIDE 36   // 36 % 32 == 4 -> frag banks = (4r+tq) all distinct
#define BS_STRIDE 72   // 72 % 32 == 8 -> frag banks = (8tq+r) all distinct

__global__ __launch_bounds__(256)
void gemm_tf32_kernel(const float* __restrict__ A, const float* __restrict__ B,
                      const float* __restrict__ bias, float* __restrict__ C,
                      int M, int N, int K, int useBias)
{
    __shared__ unsigned As[TBM * AS_STRIDE];   // [m][k], stride 36
    __shared__ unsigned Bs[TBK * BS_STRIDE];   // [k][n], stride 72

    const int tid  = threadIdx.x;
    const int lane = tid & 31;
    const int warp = tid >> 5;
    const int r    = lane >> 2;     // 0..7
    const int tq   = lane & 3;      // 0..3
    const int wm   = warp & 3;      // 0..3 : M direction
    const int wn   = warp >> 2;     // 0..1 : N direction
    const int warpM = wm * 32;
    const int warpN = wn * 32;

    const int n0 = blockIdx.x * TBN;
    const int m0 = blockIdx.y * TBM;

    float acc[2][4][4];
#pragma unroll
    for (int i = 0; i < 2; i++)
#pragma unroll
        for (int j = 0; j < 4; j++)
#pragma unroll
            for (int t = 0; t < 4; t++) acc[i][j][t] = 0.f;

    for (int k0 = 0; k0 < K; k0 += TBK) {
        // ---- load A tile: 128 rows x 32 k = 1024 float4 (4 per thread)
#pragma unroll
        for (int i = 0; i < 4; i++) {
            int f   = tid + i * 256;          // 0..1023
            int row = f >> 3;                 // 0..127
            int kk  = (f & 7) * 4;            // 0..28
            float4 v = *(const float4*)(A + (size_t)(m0 + row) * K + k0 + kk);
            unsigned* p = &As[row * AS_STRIDE + kk];
            p[0] = f2tf32(v.x); p[1] = f2tf32(v.y);
            p[2] = f2tf32(v.z); p[3] = f2tf32(v.w);
        }
        // ---- load B tile: 32 k x 64 n = 512 float4 (2 per thread)
#pragma unroll
        for (int i = 0; i < 2; i++) {
            int f   = tid + i * 256;          // 0..511
            int kk  = f >> 4;                 // 0..31
            int nn  = (f & 15) * 4;           // 0..60
            float4 v = *(const float4*)(B + (size_t)(k0 + kk) * N + n0 + nn);
            unsigned* p = &Bs[kk * BS_STRIDE + nn];
            p[0] = f2tf32(v.x); p[1] = f2tf32(v.y);
            p[2] = f2tf32(v.z); p[3] = f2tf32(v.w);
        }
        __syncthreads();

        // ---- compute: 4 k-steps of 8
#pragma unroll
        for (int ks = 0; ks < 4; ks++) {
            int kb = ks * 8;
            unsigned afrag[2][4];
#pragma unroll
            for (int mt = 0; mt < 2; mt++) {
                int rb = warpM + mt * 16;
                afrag[mt][0] = As[(rb + r)     * AS_STRIDE + kb + tq];
                afrag[mt][1] = As[(rb + r + 8) * AS_STRIDE + kb + tq];
                afrag[mt][2] = As[(rb + r)     * AS_STRIDE + kb + tq + 4];
                afrag[mt][3] = As[(rb + r + 8) * AS_STRIDE + kb + tq + 4];
            }
            unsigned bfrag[4][2];
#pragma unroll
            for (int nt = 0; nt < 4; nt++) {
                int cb = warpN + nt * 8;
                bfrag[nt][0] = Bs[(kb + tq)     * BS_STRIDE + cb + r];
                bfrag[nt][1] = Bs[(kb + tq + 4) * BS_STRIDE + cb + r];
            }
#pragma unroll
            for (int mt = 0; mt < 2; mt++)
#pragma unroll
                for (int nt = 0; nt < 4; nt++)
                    mma_tf32(acc[mt][nt], afrag[mt], bfrag[nt]);
        }
        __syncthreads();
    }

    // ---- epilogue: c0/c1 at (r, 2tq), c2/c3 at (r+8, 2tq)
#pragma unroll
    for (int mt = 0; mt < 2; mt++) {
#pragma unroll
        for (int nt = 0; nt < 4; nt++) {
            int row = m0 + warpM + mt * 16 + r;
            int col = n0 + warpN + nt * 8 + 2 * tq;
            float2 lo = make_float2(acc[mt][nt][0], acc[mt][nt][1]);
            float2 hi = make_float2(acc[mt][nt][2], acc[mt][nt][3]);
            if (useBias) {
                float2 bv = *(const float2*)(bias + col);
                lo.x += bv.x; lo.y += bv.y;
                hi.x += bv.x; hi.y += bv.y;
            }
            *(float2*)(C + (size_t)row * N + col)       = lo;
            *(float2*)(C + (size_t)(row + 8) * N + col) = hi;
        }
    }
}

// ---------------- scores: S[b,h,n,m] = SCALE * dot(q[n], k[m]) --------------
__global__ __launch_bounds__(256)
void scores_kernel(const float* __restrict__ qkv, float* __restrict__ attn)
{
    __shared__ float Qs[64][33];
    __shared__ float Ks[64][33];

    int bh = blockIdx.z;
    int b = bh / HEADS, h = bh % HEADS;
    int n0 = blockIdx.y * 32;
    int m0 = blockIdx.x * 32;
    const float* qb = qkv + (size_t)b * SEQ * QKV3 + h * HD;
    const float* kb = qb + DIMC;

    int tid = threadIdx.x;
#pragma unroll
    for (int it = 0; it < 2; it++) {
        int idx = it * 256 + tid;
        int row = idx >> 4;
        int kc  = (idx & 15) * 4;
        float4 qv = make_float4(0.f, 0.f, 0.f, 0.f);
        float4 kv = make_float4(0.f, 0.f, 0.f, 0.f);
        int nq = n0 + row, nk = m0 + row;
        if (nq < SEQ) qv = *(const float4*)(qb + (size_t)nq * QKV3 + kc);
        if (nk < SEQ) kv = *(const float4*)(kb + (size_t)nk * QKV3 + kc);
        Qs[kc + 0][row] = qv.x; Qs[kc + 1][row] = qv.y;
        Qs[kc + 2][row] = qv.z; Qs[kc + 3][row] = qv.w;
        Ks[kc + 0][row] = kv.x; Ks[kc + 1][row] = kv.y;
        Ks[kc + 2][row] = kv.z; Ks[kc + 3][row] = kv.w;
    }
    __syncthreads();

    int tx = tid & 15, ty = tid >> 4;
    float acc[2][2] = {{0.f, 0.f}, {0.f, 0.f}};
#pragma unroll
    for (int kk = 0; kk < 64; kk++) {
        float a0 = Qs[kk][ty * 2 + 0];
        float a1 = Qs[kk][ty * 2 + 1];
        float b0 = Ks[kk][tx * 2 + 0];
        float b1 = Ks[kk][tx * 2 + 1];
        acc[0][0] += a0 * b0; acc[0][1] += a0 * b1;
        acc[1][0] += a1 * b0; acc[1][1] += a1 * b1;
    }

    float* out = attn + (size_t)bh * SEQ * SEQ;
#pragma unroll
    for (int i = 0; i < 2; i++) {
        int n = n0 + ty * 2 + i;
        if (n >= SEQ) continue;
#pragma unroll
        for (int j = 0; j < 2; j++) {
            int m = m0 + tx * 2 + j;
            if (m < SEQ) out[(size_t)n * SEQ + m] = acc[i][j] * SCALE;
        }
    }
}

// ---------------- softmax (axis m) + static_a bias, in place ----------------
__global__ __launch_bounds__(256)
void softmax_bias_kernel(float* __restrict__ attn, const float* __restrict__ sa)
{
    int row = blockIdx.x;
    int n   = row % SEQ;
    int bh  = row / SEQ;
    int h   = bh % HEADS;
    float* p = attn + (size_t)row * SEQ;
    int tid = threadIdx.x;

    float v = (tid < SEQ) ? p[tid] : -INFINITY;

    __shared__ float red[256];
    red[tid] = v;
    __syncthreads();
#pragma unroll
    for (int s = 128; s > 0; s >>= 1) {
        if (tid < s) red[tid] = fmaxf(red[tid], red[tid + s]);
        __syncthreads();
    }
    float mx = red[0];
    __syncthreads();

    float e = (tid < SEQ) ? __expf(v - mx) : 0.f;
    red[tid] = e;
    __syncthreads();
#pragma unroll
    for (int s = 128; s > 0; s >>= 1) {
        if (tid < s) red[tid] += red[tid + s];
        __syncthreads();
    }
    float inv = 1.f / red[0];

    if (tid < SEQ)
        p[tid] = e * inv + sa[((size_t)h * SEQ + n) * SEQ + tid];
}

// ---------------- AV ---------------------------------------------------------
__global__ __launch_bounds__(256)
void av_kernel(const float* __restrict__ attn, const float* __restrict__ qkv,
               float* __restrict__ ao)
{
    __shared__ float Sts[16][33];
    __shared__ float Vts[16][64];

    int bh = blockIdx.y;
    int b = bh / HEADS, h = bh % HEADS;
    int n0 = blockIdx.x * 32;
    const float* Sb = attn + (size_t)bh * SEQ * SEQ;
    const float* Vb = qkv + (size_t)b * SEQ * QKV3 + 2 * DIMC + h * HD;

    int tid = threadIdx.x;
    int tx = tid & 15, ty = tid >> 4;
    float acc[2][4];
#pragma unroll
    for (int i = 0; i < 2; i++)
#pragma unroll
        for (int j = 0; j < 4; j++) acc[i][j] = 0.f;

    for (int k0 = 0; k0 < SEQ; k0 += 16) {
        if (tid < 128) {
            int row = tid >> 2;
            int kc  = (tid & 3) * 4;
            float4 sv = make_float4(0.f, 0.f, 0.f, 0.f);
            int n = n0 + row;
            if (n < SEQ) {
                if (k0 + kc + 3 < SEQ) {
                    sv = *(const float4*)(Sb + (size_t)n * SEQ + k0 + kc);
                } else {
                    float t[4] = {0.f, 0.f, 0.f, 0.f};
#pragma unroll
                    for (int i = 0; i < 4; i++)
                        if (k0 + kc + i < SEQ) t[i] = Sb[(size_t)n * SEQ + k0 + kc + i];
                    sv = make_float4(t[0], t[1], t[2], t[3]);
                }
            }
            Sts[kc + 0][row] = sv.x; Sts[kc + 1][row] = sv.y;
            Sts[kc + 2][row] = sv.z; Sts[kc + 3][row] = sv.w;
        }
        {
            int kk = tid >> 4;
            int c  = (tid & 15) * 4;
            float4 vv = make_float4(0.f, 0.f, 0.f, 0.f);
            if (k0 + kk < SEQ)
                vv = *(const float4*)(Vb + (size_t)(k0 + kk) * QKV3 + c);
            *(float4*)&Vts[kk][c] = vv;
        }
        __syncthreads();

#pragma unroll
        for (int kk = 0; kk < 16; kk++) {
            float a0 = Sts[kk][ty * 2 + 0];
            float a1 = Sts[kk][ty * 2 + 1];
            float4 bv = *(const float4*)&Vts[kk][tx * 4];
            acc[0][0] += a0 * bv.x; acc[0][1] += a0 * bv.y;
            acc[0][2] += a0 * bv.z; acc[0][3] += a0 * bv.w;
            acc[1][0] += a1 * bv.x; acc[1][1] += a1 * bv.y;
            acc[1][2] += a1 * bv.z; acc[1][3] += a1 * bv.w;
        }
        __syncthreads();
    }

    float* ob = ao + (size_t)b * SEQ * DIMC + h * HD;
#pragma unroll
    for (int i = 0; i < 2; i++) {
        int n = n0 + ty * 2 + i;
        if (n < SEQ) {
            float4 r = make_float4(acc[i][0], acc[i][1], acc[i][2], acc[i][3]);
            *(float4*)(ob + (size_t)n * DIMC + tx * 4) = r;
        }
    }
}

// ---------------- launch ----------------------------------------------------
extern "C" void kernel_launch(void* const* d_in, const int* in_sizes, int n_in,
                              void* d_out, int out_size)
{
    const float* x     = (const float*)d_in[0];  // [64,196,768]
    const float* Wqkv  = (const float*)d_in[1];  // [768,2304]
    const float* sa    = (const float*)d_in[2];  // [1,12,196,196]
    const float* Wproj = (const float*)d_in[3];  // [768,768]
    const float* bproj = (const float*)d_in[4];  // [768]
    float* out = (float*)d_out;                  // [64,196,768]

    void *p_qkv, *p_attn, *p_ao;
    cudaGetSymbolAddress(&p_qkv, g_qkv);
    cudaGetSymbolAddress(&p_attn, g_attn);
    cudaGetSymbolAddress(&p_ao, g_ao);
    float* qkv  = (float*)p_qkv;
    float* attn = (float*)p_attn;
    float* ao   = (float*)p_ao;

    // 1) QKV GEMM: [12544,768] @ [768,2304]  (tf32 tensor path)
    gemm_tf32_kernel<<<dim3(QKV3 / TBN, BN / TBM), 256>>>(x, Wqkv, nullptr, qkv,
                                                          BN, QKV3, DIMC, 0);
    // 2) scores
    scores_kernel<<<dim3(7, 7, BATCH * HEADS), 256>>>(qkv, attn);
    // 3) softmax + static_a
    softmax_bias_kernel<<<BATCH * HEADS * SEQ, 256>>>(attn, sa);
    // 4) AV
    av_kernel<<<dim3(7, BATCH * HEADS), 256>>>(attn, qkv, ao);
    // 5) output projection + bias (tf32 tensor path)
    gemm_tf32_kernel<<<dim3(DIMC / TBN, BN / TBM), 256>>>(ao, Wproj, bproj, out,
                                                          BN, DIMC, DIMC, 1);
}

// round 3
// speedup vs baseline: 2.7820x; 1.5457x over previous
#include <cuda_runtime.h>
#include <cuda_bf16.h>
#include <math.h>

#define BATCH 64
#define SEQ   196
#define DIMC  768
#define HEADS 12
#define HD    64
#define QKV3  2304           // 3*DIMC
#define BN    (BATCH*SEQ)    // 12544
#define SCALE 0.125f         // HD^-0.5

// ---------------- scratch (no allocation allowed; __device__ globals) -------
__device__ float g_qkv[(size_t)BATCH * SEQ * QKV3];           // [BN, 2304]
__device__ float g_ao[(size_t)BATCH * SEQ * DIMC];            // [BN, 768]

// ---------------- tf32 helpers ----------------------------------------------
__device__ __forceinline__ unsigned f2tf32(float x) {
    unsigned u;
    asm volatile("cvt.rna.tf32.f32 %0, %1;" : "=r"(u) : "f"(x));
    return u;
}

__device__ __forceinline__ void mma_tf32(float (&d)[4], const unsigned (&a)[4],
                                         const unsigned (&b)[2]) {
    asm volatile(
        "mma.sync.aligned.m16n8k8.row.col.f32.tf32.tf32.f32 "
        "{%0,%1,%2,%3}, {%4,%5,%6,%7}, {%8,%9}, {%0,%1,%2,%3};\n"
        : "+f"(d[0]), "+f"(d[1]), "+f"(d[2]), "+f"(d[3])
        : "r"(a[0]), "r"(a[1]), "r"(a[2]), "r"(a[3]), "r"(b[0]), "r"(b[1]));
}

// ---------------- TF32 GEMM: C[M,N] = A[M,K] @ B[K,N] (+bias) ---------------
#define TBM 128
#define TBN 64
#define TBK 32
#define AS_STRIDE 36
#define BS_STRIDE 72

__global__ __launch_bounds__(256)
void gemm_tf32_kernel(const float* __restrict__ A, const float* __restrict__ B,
                      const float* __restrict__ bias, float* __restrict__ C,
                      int M, int N, int K, int useBias)
{
    __shared__ unsigned As[TBM * AS_STRIDE];
    __shared__ unsigned Bs[TBK * BS_STRIDE];

    const int tid  = threadIdx.x;
    const int lane = tid & 31;
    const int warp = tid >> 5;
    const int r    = lane >> 2;
    const int tq   = lane & 3;
    const int warpM = (warp & 3) * 32;
    const int warpN = (warp >> 2) * 32;

    const int n0 = blockIdx.x * TBN;
    const int m0 = blockIdx.y * TBM;

    float acc[2][4][4];
#pragma unroll
    for (int i = 0; i < 2; i++)
#pragma unroll
        for (int j = 0; j < 4; j++)
#pragma unroll
            for (int t = 0; t < 4; t++) acc[i][j][t] = 0.f;

    for (int k0 = 0; k0 < K; k0 += TBK) {
#pragma unroll
        for (int i = 0; i < 4; i++) {
            int f   = tid + i * 256;
            int row = f >> 3;
            int kk  = (f & 7) * 4;
            float4 v = *(const float4*)(A + (size_t)(m0 + row) * K + k0 + kk);
            unsigned* p = &As[row * AS_STRIDE + kk];
            p[0] = f2tf32(v.x); p[1] = f2tf32(v.y);
            p[2] = f2tf32(v.z); p[3] = f2tf32(v.w);
        }
#pragma unroll
        for (int i = 0; i < 2; i++) {
            int f   = tid + i * 256;
            int kk  = f >> 4;
            int nn  = (f & 15) * 4;
            float4 v = *(const float4*)(B + (size_t)(k0 + kk) * N + n0 + nn);
            unsigned* p = &Bs[kk * BS_STRIDE + nn];
            p[0] = f2tf32(v.x); p[1] = f2tf32(v.y);
            p[2] = f2tf32(v.z); p[3] = f2tf32(v.w);
        }
        __syncthreads();

#pragma unroll
        for (int ks = 0; ks < 4; ks++) {
            int kb = ks * 8;
            unsigned afrag[2][4];
#pragma unroll
            for (int mt = 0; mt < 2; mt++) {
                int rb = warpM + mt * 16;
                afrag[mt][0] = As[(rb + r)     * AS_STRIDE + kb + tq];
                afrag[mt][1] = As[(rb + r + 8) * AS_STRIDE + kb + tq];
                afrag[mt][2] = As[(rb + r)     * AS_STRIDE + kb + tq + 4];
                afrag[mt][3] = As[(rb + r + 8) * AS_STRIDE + kb + tq + 4];
            }
            unsigned bfrag[4][2];
#pragma unroll
            for (int nt = 0; nt < 4; nt++) {
                int cb = warpN + nt * 8;
                bfrag[nt][0] = Bs[(kb + tq)     * BS_STRIDE + cb + r];
                bfrag[nt][1] = Bs[(kb + tq + 4) * BS_STRIDE + cb + r];
            }
#pragma unroll
            for (int mt = 0; mt < 2; mt++)
#pragma unroll
                for (int nt = 0; nt < 4; nt++)
                    mma_tf32(acc[mt][nt], afrag[mt], bfrag[nt]);
        }
        __syncthreads();
    }

#pragma unroll
    for (int mt = 0; mt < 2; mt++) {
#pragma unroll
        for (int nt = 0; nt < 4; nt++) {
            int row = m0 + warpM + mt * 16 + r;
            int col = n0 + warpN + nt * 8 + 2 * tq;
            float2 lo = make_float2(acc[mt][nt][0], acc[mt][nt][1]);
            float2 hi = make_float2(acc[mt][nt][2], acc[mt][nt][3]);
            if (useBias) {
                float2 bv = *(const float2*)(bias + col);
                lo.x += bv.x; lo.y += bv.y;
                hi.x += bv.x; hi.y += bv.y;
            }
            *(float2*)(C + (size_t)row * N + col)       = lo;
            *(float2*)(C + (size_t)(row + 8) * N + col) = hi;
        }
    }
}

// ---------------- fused attention: scores + softmax(+bias) + AV -------------
// One block per (b, h, q-half of 98 rows). 512 threads = 16 warps.
// smem (floats): Qs[112][68] tf32 | KV[] (K tf32 [208][68] then V f32 [200][72]) | S[112][212] f32
#define QS_OFF 0
#define KV_OFF 7616            // 112*68
#define S_OFF  22016           // 7616 + 14400
#define FUSED_SMEM_BYTES (45760 * 4)   // 183040

__global__ __launch_bounds__(512)
void fused_attn_kernel(const float* __restrict__ qkv,
                       const float* __restrict__ sa,
                       float* __restrict__ ao)
{
    extern __shared__ float sm[];
    unsigned* Qs = (unsigned*)(sm + QS_OFF);   // [112][68]
    unsigned* Ks = (unsigned*)(sm + KV_OFF);   // [208][68] (pass 1)
    float*    Vs = sm + KV_OFF;                // [200][72] (pass 3)
    float*    S  = sm + S_OFF;                 // [112][212]

    const int bid = blockIdx.x;
    const int bh = bid >> 1, qb = bid & 1;
    const int b = bh / HEADS, h = bh % HEADS;
    const int q0 = qb * 98;

    const float* Qg = qkv + (size_t)b * SEQ * QKV3 + h * HD;
    const float* Kg = Qg + DIMC;
    const float* Vg = Qg + 2 * DIMC;

    const int tid  = threadIdx.x;
    const int lane = tid & 31;
    const int warp = tid >> 5;
    const int r    = lane >> 2;
    const int tq   = lane & 3;

    // ---- load Q (tf32), rows >= 98 zeroed
    for (int i = tid; i < 112 * 16; i += 512) {
        int row = i >> 4, c4 = (i & 15) * 4;
        float4 v = make_float4(0.f, 0.f, 0.f, 0.f);
        if (row < 98) v = *(const float4*)(Qg + (size_t)(q0 + row) * QKV3 + c4);
        unsigned* p = &Qs[row * 68 + c4];
        p[0] = f2tf32(v.x); p[1] = f2tf32(v.y);
        p[2] = f2tf32(v.z); p[3] = f2tf32(v.w);
    }
    // ---- load K (tf32), rows >= 196 zeroed
    for (int i = tid; i < 208 * 16; i += 512) {
        int row = i >> 4, c4 = (i & 15) * 4;
        float4 v = make_float4(0.f, 0.f, 0.f, 0.f);
        if (row < SEQ) v = *(const float4*)(Kg + (size_t)row * QKV3 + c4);
        unsigned* p = &Ks[row * 68 + c4];
        p[0] = f2tf32(v.x); p[1] = f2tf32(v.y);
        p[2] = f2tf32(v.z); p[3] = f2tf32(v.w);
    }
    __syncthreads();

    // ---- pass 1: S[112][208] = Q @ K^T * SCALE  (items: 7 ntiles x 13 mgroups)
    for (int item = warp; item < 7 * 13; item += 16) {
        int nt = item / 13, mg = item % 13;
        float acc[2][4] = {{0.f,0.f,0.f,0.f},{0.f,0.f,0.f,0.f}};
#pragma unroll
        for (int ks = 0; ks < 8; ks++) {
            int kb = ks * 8;
            unsigned af[4];
            af[0] = Qs[(nt * 16 + r)     * 68 + kb + tq];
            af[1] = Qs[(nt * 16 + r + 8) * 68 + kb + tq];
            af[2] = Qs[(nt * 16 + r)     * 68 + kb + tq + 4];
            af[3] = Qs[(nt * 16 + r + 8) * 68 + kb + tq + 4];
#pragma unroll
            for (int mt = 0; mt < 2; mt++) {
                int cb = mg * 16 + mt * 8;
                unsigned bf[2];
                bf[0] = Ks[(cb + r) * 68 + kb + tq];
                bf[1] = Ks[(cb + r) * 68 + kb + tq + 4];
                mma_tf32(acc[mt], af, bf);
            }
        }
#pragma unroll
        for (int mt = 0; mt < 2; mt++) {
            int c = mg * 16 + mt * 8 + 2 * tq;
            int row = nt * 16 + r;
            S[row * 212 + c]         = acc[mt][0] * SCALE;
            S[row * 212 + c + 1]     = acc[mt][1] * SCALE;
            S[(row + 8) * 212 + c]     = acc[mt][2] * SCALE;
            S[(row + 8) * 212 + c + 1] = acc[mt][3] * SCALE;
        }
    }
    __syncthreads();

    // ---- load V (fp32) into KV buffer, stride 72, rows 0..199 (>=196 zero)
    for (int i = tid; i < 200 * 16; i += 512) {
        int row = i >> 4, c4 = (i & 15) * 4;
        float4 v = make_float4(0.f, 0.f, 0.f, 0.f);
        if (row < SEQ) v = *(const float4*)(Vg + (size_t)row * QKV3 + c4);
        *(float4*)&Vs[row * 72 + c4] = v;
    }

    // ---- pass 2: softmax rows (cols<196) + static_a bias, in place
    for (int row = warp; row < 98; row += 16) {
        float* Sr = S + row * 212;
        float vals[7];
        float mx = -INFINITY;
#pragma unroll
        for (int j = 0; j < 7; j++) {
            int c = lane + 32 * j;
            vals[j] = (c < SEQ) ? Sr[c] : -INFINITY;
            mx = fmaxf(mx, vals[j]);
        }
#pragma unroll
        for (int s = 16; s; s >>= 1) mx = fmaxf(mx, __shfl_xor_sync(0xffffffffu, mx, s));
        float sum = 0.f;
#pragma unroll
        for (int j = 0; j < 7; j++) { vals[j] = __expf(vals[j] - mx); sum += vals[j]; }
#pragma unroll
        for (int s = 16; s; s >>= 1) sum += __shfl_xor_sync(0xffffffffu, sum, s);
        float inv = 1.f / sum;
        const float* ar = sa + ((size_t)h * SEQ + q0 + row) * SEQ;
#pragma unroll
        for (int j = 0; j < 7; j++) {
            int c = lane + 32 * j;
            if (c < SEQ) Sr[c] = vals[j] * inv + ar[c];
        }
    }
    __syncthreads();

    // ---- pass 3: out = S(98x196) @ V(196x64), 3xTF32 split
    float* og = ao + (size_t)b * SEQ * DIMC + h * HD;
    for (int item = warp; item < 7 * 4; item += 16) {
        int nt = item >> 2, cg = item & 3;
        float acc[2][4] = {{0.f,0.f,0.f,0.f},{0.f,0.f,0.f,0.f}};
        for (int ks = 0; ks < 25; ks++) {
            int kb = ks * 8;
            float av[4];
            av[0] = S[(nt * 16 + r)     * 212 + kb + tq];
            av[1] = S[(nt * 16 + r + 8) * 212 + kb + tq];
            av[2] = S[(nt * 16 + r)     * 212 + kb + tq + 4];
            av[3] = S[(nt * 16 + r + 8) * 212 + kb + tq + 4];
            unsigned ahi[4], alo[4];
#pragma unroll
            for (int i = 0; i < 4; i++) {
                ahi[i] = f2tf32(av[i]);
                alo[i] = f2tf32(av[i] - __uint_as_float(ahi[i]));
            }
#pragma unroll
            for (int mt = 0; mt < 2; mt++) {
                int cb = cg * 16 + mt * 8;
                float b0 = Vs[(kb + tq)     * 72 + cb + r];
                float b1 = Vs[(kb + tq + 4) * 72 + cb + r];
                unsigned bhi[2], blo[2];
                bhi[0] = f2tf32(b0); bhi[1] = f2tf32(b1);
                blo[0] = f2tf32(b0 - __uint_as_float(bhi[0]));
                blo[1] = f2tf32(b1 - __uint_as_float(bhi[1]));
                mma_tf32(acc[mt], ahi, bhi);
                mma_tf32(acc[mt], ahi, blo);
                mma_tf32(acc[mt], alo, bhi);
            }
        }
#pragma unroll
        for (int mt = 0; mt < 2; mt++) {
            int c = cg * 16 + mt * 8 + 2 * tq;
            int row = nt * 16 + r;
            if (row < 98)
                *(float2*)(og + (size_t)(q0 + row) * DIMC + c) =
                    make_float2(acc[mt][0], acc[mt][1]);
            if (row + 8 < 98)
                *(float2*)(og + (size_t)(q0 + row + 8) * DIMC + c) =
                    make_float2(acc[mt][2], acc[mt][3]);
        }
    }
}

// ---------------- launch ----------------------------------------------------
extern "C" void kernel_launch(void* const* d_in, const int* in_sizes, int n_in,
                              void* d_out, int out_size)
{
    const float* x     = (const float*)d_in[0];  // [64,196,768]
    const float* Wqkv  = (const float*)d_in[1];  // [768,2304]
    const float* sa    = (const float*)d_in[2];  // [1,12,196,196]
    const float* Wproj = (const float*)d_in[3];  // [768,768]
    const float* bproj = (const float*)d_in[4];  // [768]
    float* out = (float*)d_out;                  // [64,196,768]

    void *p_qkv, *p_ao;
    cudaGetSymbolAddress(&p_qkv, g_qkv);
    cudaGetSymbolAddress(&p_ao, g_ao);
    float* qkv = (float*)p_qkv;
    float* ao  = (float*)p_ao;

    static int smem_set = 0;
    if (!smem_set) {
        cudaFuncSetAttribute(fused_attn_kernel,
                             cudaFuncAttributeMaxDynamicSharedMemorySize,
                             FUSED_SMEM_BYTES);
        smem_set = 1;
    }

    // 1) QKV GEMM: [12544,768] @ [768,2304]  (tf32 tensor path)
    gemm_tf32_kernel<<<dim3(QKV3 / TBN, BN / TBM), 256>>>(x, Wqkv, nullptr, qkv,
                                                          BN, QKV3, DIMC, 0);
    // 2-4) fused scores + softmax(+static_a) + AV
    fused_attn_kernel<<<BATCH * HEADS * 2, 512, FUSED_SMEM_BYTES>>>(qkv, sa, ao);
    // 5) output projection + bias (tf32 tensor path)
    gemm_tf32_kernel<<<dim3(DIMC / TBN, BN / TBM), 256>>>(ao, Wproj, bproj, out,
                                                          BN, DIMC, DIMC, 1);
}